// round 1
// baseline (speedup 1.0000x reference)
#include <cuda_runtime.h>
#include <math.h>

// ---------------- problem constants ----------------
#define BATCH   2
#define SEQ     512
#define DM      768
#define DI      1536          // d_inner
#define DS      16            // d_state
#define M_TOT   (BATCH*SEQ)   // 1024
#define XZ_LD   (2*DI)        // 3072
#define XDBL_LD (DI + 2*DS)   // 1568

// ---------------- scratch (static __device__, no allocs) ----------------
__device__ float g_xz   [M_TOT * XZ_LD];    // 12.6 MB : [bt][2*DI]  (x_inner | z)
__device__ float g_xconv[M_TOT * DI];       //  6.3 MB : [bt][DI]
__device__ float g_xdbl [M_TOT * XDBL_LD];  //  6.4 MB : [bt][1568]  (delta_raw | B | C)
__device__ float g_delta[M_TOT * DI];       //  6.3 MB : [bt][DI]    softplus'd delta
__device__ float g_ypreT[DI * M_TOT];       //  6.3 MB : [d][b*SEQ+t] (transposed for final GEMM)

__device__ __forceinline__ float softplusf(float x) {
    if (x > 20.f) return x;
    return log1pf(expf(x));
}
__device__ __forceinline__ float siluf(float x) {
    return x / (1.f + expf(-x));
}

// ---------------- generic tiled GEMM: C[M,N] = act(A @ W^T (+bias)) ----------------
// A: row-major [M,K] (lda)  OR column-major [K,M] (lda = M stride) when ACOL
// W: row-major [N,K] (ldw)  -> computes A @ W^T
// 64x64 tile, BK=16, 256 threads, 4x4 per thread.
template <bool ACOL, bool SP>
__global__ __launch_bounds__(256)
void gemm64(const float* __restrict__ A, int lda,
            const float* __restrict__ W, int ldw,
            const float* __restrict__ bias,
            float* __restrict__ C, int ldc,
            int N, int K)
{
    __shared__ float As[16][68];
    __shared__ float Ws[16][68];

    const int bm = blockIdx.y * 64;
    const int bn = blockIdx.x * 64;
    const int tid = threadIdx.x;
    const int tx = tid & 15;     // 0..15 -> 4 cols
    const int ty = tid >> 4;     // 0..15 -> 4 rows

    // loader indices (row-major A / W): 64 rows x 4 float4
    const int lrow = tid >> 2;         // 0..63
    const int lk4  = (tid & 3) * 4;    // 0,4,8,12
    // loader indices (col-major A): 16 k-rows x 16 float4 along m
    const int akrow = tid >> 4;        // 0..15
    const int am4   = (tid & 15) * 4;  // 0..60

    const bool wok = (bn + lrow) < N;

    float acc[4][4];
#pragma unroll
    for (int i = 0; i < 4; i++)
#pragma unroll
        for (int j = 0; j < 4; j++) acc[i][j] = 0.f;

    for (int k0 = 0; k0 < K; k0 += 16) {
        float4 av, wv;
        if (ACOL) {
            av = *(const float4*)(A + (size_t)(k0 + akrow) * lda + bm + am4);
        } else {
            av = *(const float4*)(A + (size_t)(bm + lrow) * lda + k0 + lk4);
        }
        if (wok) wv = *(const float4*)(W + (size_t)(bn + lrow) * ldw + k0 + lk4);
        else     wv = make_float4(0.f, 0.f, 0.f, 0.f);

        __syncthreads();
        if (ACOL) {
            *(float4*)&As[akrow][am4] = av;
        } else {
            As[lk4 + 0][lrow] = av.x; As[lk4 + 1][lrow] = av.y;
            As[lk4 + 2][lrow] = av.z; As[lk4 + 3][lrow] = av.w;
        }
        Ws[lk4 + 0][lrow] = wv.x; Ws[lk4 + 1][lrow] = wv.y;
        Ws[lk4 + 2][lrow] = wv.z; Ws[lk4 + 3][lrow] = wv.w;
        __syncthreads();

#pragma unroll
        for (int kk = 0; kk < 16; kk++) {
            float4 a4 = *(const float4*)&As[kk][ty * 4];
            float4 b4 = *(const float4*)&Ws[kk][tx * 4];
            float a[4] = {a4.x, a4.y, a4.z, a4.w};
            float b[4] = {b4.x, b4.y, b4.z, b4.w};
#pragma unroll
            for (int i = 0; i < 4; i++)
#pragma unroll
                for (int j = 0; j < 4; j++)
                    acc[i][j] = fmaf(a[i], b[j], acc[i][j]);
        }
    }

#pragma unroll
    for (int i = 0; i < 4; i++) {
        const int row = bm + ty * 4 + i;
#pragma unroll
        for (int j = 0; j < 4; j++) {
            const int col = bn + tx * 4 + j;
            if (col < N) {
                float v = acc[i][j];
                if (SP) v = softplusf(v + bias[col]);
                C[(size_t)row * ldc + col] = v;
            }
        }
    }
}

// ---------------- depthwise causal conv (k=4) + bias + SiLU ----------------
__global__ __launch_bounds__(256)
void conv_silu_kernel(const float* __restrict__ conv_w, const float* __restrict__ conv_b)
{
    const int idx = blockIdx.x * 256 + threadIdx.x;   // over M_TOT*DI
    const int d  = idx % DI;
    const int bt = idx / DI;
    const int b = bt / SEQ, t = bt % SEQ;

    const float w0 = conv_w[d * 4 + 0];
    const float w1 = conv_w[d * 4 + 1];
    const float w2 = conv_w[d * 4 + 2];
    const float w3 = conv_w[d * 4 + 3];

    const float* base = g_xz + (size_t)(b * SEQ) * XZ_LD + d;
    float s = conv_b[d];
    if (t >= 3) s = fmaf(base[(size_t)(t - 3) * XZ_LD], w0, s);
    if (t >= 2) s = fmaf(base[(size_t)(t - 2) * XZ_LD], w1, s);
    if (t >= 1) s = fmaf(base[(size_t)(t - 1) * XZ_LD], w2, s);
    s = fmaf(base[(size_t)t * XZ_LD], w3, s);
    g_xconv[(size_t)bt * DI + d] = siluf(s);
}

// ---------------- fused selective-scan kernel ----------------
// Grid: (DI, BATCH), 512 threads (16 warps, warp w owns state n=w).
// Replicates the reference's (non-associative) Blelloch up/down sweep, in
// LINEAR space (mathematically identical to the log-space version).
// Epilogue fuses: sum_n h*C  + x_conv*Dp, * silu(z), transposed store.
#define WPAD 528   // 512 + 16 pad (idx + idx>>5)
__global__ __launch_bounds__(512)
void scan_kernel(const float* __restrict__ A_log, const float* __restrict__ Dp)
{
    const int d = blockIdx.x;
    const int b = blockIdx.y;
    extern __shared__ float sm[];
    float* sdelta = sm;              // [512]
    float* sxc    = sm + SEQ;        // [512]
    const int tid  = threadIdx.x;
    const int warp = tid >> 5;
    const int lane = tid & 31;
    float* cw = sm + 2 * SEQ + warp * (2 * WPAD);
    float* vw = cw + WPAD;

    // load delta & x_conv columns (strided gmem, L2-resident)
    {
        const int t = tid;
        sdelta[t] = g_delta[(size_t)(b * SEQ + t) * DI + d];
        sxc[t]    = g_xconv[(size_t)(b * SEQ + t) * DI + d];
    }
    __syncthreads();

    const int n = warp;                          // state index 0..15
    const float a = -expf(A_log[d * DS + n]);

    // build c[t], v[t]
    for (int t = lane; t < SEQ; t += 32) {
        const float dt = sdelta[t];
        const float Bt = g_xdbl[(size_t)(b * SEQ + t) * XDBL_LD + DI + n];
        cw[t + (t >> 5)] = expf(dt * a) + 1e-12f;
        vw[t + (t >> 5)] = fabsf(dt * Bt * sxc[t]) + 1e-12f;
    }
    __syncwarp();

    // up-sweep (9 levels), exact replica of reference ordering
#pragma unroll
    for (int lev = 0; lev < 9; lev++) {
        const int half = 1 << lev;
        const int np   = SEQ >> (lev + 1);
        for (int i = lane; i < np; i += 32) {
            const int r = ((i + 1) << (lev + 1)) - 1;
            const int l = r - half;
            const int pr = r + (r >> 5), pl = l + (l >> 5);
            const float cl = cw[pl], cr = cw[pr];
            const float vl = vw[pl], vr = vw[pr];
            vw[pr] = fmaf(cr, vr, vl);   // v_r = v_l + c_r_old * v_r
            cw[pr] = cl * cr;
        }
        __syncwarp();
    }
    // down-sweep
#pragma unroll
    for (int lev = 8; lev >= 0; lev--) {
        const int half = 1 << lev;
        const int np   = SEQ >> (lev + 1);
        for (int i = lane; i < np; i += 32) {
            const int r = ((i + 1) << (lev + 1)) - 1;
            const int l = r - half;
            const int pr = r + (r >> 5), pl = l + (l >> 5);
            const float vr = vw[pr];
            const float vl = vw[pl];
            const float cr = cw[pr];
            vw[pr] = fmaf(cr, vr, vl);
            vw[pl] = vr;
        }
        __syncwarp();
    }

    // multiply by C (per state)
    for (int t = lane; t < SEQ; t += 32) {
        const float Ct = g_xdbl[(size_t)(b * SEQ + t) * XDBL_LD + DI + DS + n];
        vw[t + (t >> 5)] *= Ct;
    }
    __syncthreads();

    // reduce across 16 states + epilogue, transposed coalesced store
    {
        const int t = tid;
        const int pt = t + (t >> 5);
        float acc = 0.f;
#pragma unroll
        for (int w = 0; w < 16; w++)
            acc += sm[2 * SEQ + w * (2 * WPAD) + WPAD + pt];
        const float z  = g_xz[(size_t)(b * SEQ + t) * XZ_LD + DI + d];
        float yv = fmaf(sxc[t], Dp[d], acc);
        yv *= siluf(z);
        g_ypreT[(size_t)d * M_TOT + b * SEQ + t] = yv;
    }
}

// ---------------- launch ----------------
extern "C" void kernel_launch(void* const* d_in, const int* in_sizes, int n_in,
                              void* d_out, int out_size)
{
    const float* x      = (const float*)d_in[0];
    const float* W_in   = (const float*)d_in[1];
    const float* conv_w = (const float*)d_in[2];
    const float* conv_b = (const float*)d_in[3];
    const float* W_x    = (const float*)d_in[4];
    const float* W_dt   = (const float*)d_in[5];
    const float* b_dt   = (const float*)d_in[6];
    const float* A_log  = (const float*)d_in[7];
    const float* Dp     = (const float*)d_in[8];
    const float* W_out  = (const float*)d_in[9];
    float* out = (float*)d_out;

    float *xz, *xconv, *xdbl, *delta, *ypreT;
    cudaGetSymbolAddress((void**)&xz,    g_xz);
    cudaGetSymbolAddress((void**)&xconv, g_xconv);
    cudaGetSymbolAddress((void**)&xdbl,  g_xdbl);
    cudaGetSymbolAddress((void**)&delta, g_delta);
    cudaGetSymbolAddress((void**)&ypreT, g_ypreT);

    const int scan_smem = (2 * SEQ + 16 * 2 * WPAD) * sizeof(float);  // 71680 B
    cudaFuncSetAttribute(scan_kernel, cudaFuncAttributeMaxDynamicSharedMemorySize, scan_smem);

    // 1) xz = x @ W_in^T    [1024, 3072]
    gemm64<false, false><<<dim3(XZ_LD / 64, M_TOT / 64), 256>>>(
        x, DM, W_in, DM, nullptr, xz, XZ_LD, XZ_LD, DM);

    // 2) depthwise causal conv + bias + silu -> x_conv [1024, 1536]
    conv_silu_kernel<<<(M_TOT * DI) / 256, 256>>>(conv_w, conv_b);

    // 3) x_dbl = x_conv @ W_x^T   [1024, 1568]
    gemm64<false, false><<<dim3((XDBL_LD + 63) / 64, M_TOT / 64), 256>>>(
        xconv, DI, W_x, DI, nullptr, xdbl, XDBL_LD, XDBL_LD, DI);

    // 4) delta = softplus(delta_raw @ W_dt^T + b_dt)   [1024, 1536]
    gemm64<false, true><<<dim3(DI / 64, M_TOT / 64), 256>>>(
        xdbl, XDBL_LD, W_dt, DI, b_dt, delta, DI, DI, DI);

    // 5) fused scan + C-reduction + Dp + silu(z) gate -> ypreT [1536, 1024]
    scan_kernel<<<dim3(DI, BATCH), 512, scan_smem>>>(A_log, Dp);

    // 6) out = ypre @ W_out^T   [1024, 768]  (A column-major via ypreT)
    gemm64<true, false><<<dim3(DM / 64, M_TOT / 64), 256>>>(
        ypreT, M_TOT, W_out, DI, nullptr, out, DM, DM, DI);
}